// round 3
// baseline (speedup 1.0000x reference)
#include <cuda_runtime.h>
#include <cuda_bf16.h>
#include <math.h>

// ---------------- problem constants ----------------
#define NB   8
#define NS   256
#define NP   16
#define ND   512
#define NH   8
#define HD   64
#define NL   6
#define NF   2048
#define NV   65536
#define NTOK (NB * NS)   // 2048

// ---------------- scratch (device globals; no allocation) ----------------
__device__ float g_x  [NTOK * ND];
__device__ float g_xn [NTOK * ND];
__device__ float g_qkv[NTOK * 3 * ND];
__device__ float g_o  [NTOK * ND];
__device__ float g_h  [NTOK * NF];

// ---------------- tokenize + embed ----------------
__global__ void tokenize_embed_kernel(const float* __restrict__ patches,
                                      const float* __restrict__ masked_token,
                                      const float* __restrict__ partial_params,
                                      const float* __restrict__ emb_w,
                                      const float* __restrict__ emb_b) {
    const int tok = blockIdx.x;
    const int tid = threadIdx.x;   // 128 threads
    __shared__ float proc[NP];

    if (tid == 0) {
        const float* f = patches + (size_t)tok * NP;
        bool anyMask = false, anyBin = false;
        int firstBin = -1;
        float fp[NP];
        #pragma unroll
        for (int p = 0; p < NP; p++) {
            float v = f[p];
            fp[p] = v;
            bool m = fabsf(v - 0.5f) < 0.1f;
            if (m) anyMask = true;
            else { anyBin = true; if (firstBin < 0) firstBin = p; }
        }
        if (!anyBin) {
            #pragma unroll
            for (int p = 0; p < NP; p++) proc[p] = masked_token[p];
        } else if (anyMask) {
            int ptok = firstBin * 2 + (int)rintf(fp[firstBin]);
            const float* pp = partial_params + ptok * NP;
            #pragma unroll
            for (int p = 0; p < NP; p++) proc[p] = pp[p];
        } else {
            #pragma unroll
            for (int p = 0; p < NP; p++) proc[p] = fp[p];
        }
    }
    __syncthreads();

    for (int d = tid; d < ND; d += blockDim.x) {
        const float* w = emb_w + d * NP;
        float s = emb_b[d];
        #pragma unroll
        for (int p = 0; p < NP; p++) s += proc[p] * w[p];
        g_x[(size_t)tok * ND + d] = s;
    }
}

// ---------------- layernorm ----------------
__global__ void ln_kernel(const float* __restrict__ in, float* __restrict__ out,
                          const float* __restrict__ gamma, const float* __restrict__ beta) {
    const int tok = blockIdx.x;
    const int tid = threadIdx.x;   // 256
    const float2 v = ((const float2*)(in + (size_t)tok * ND))[tid];

    float s  = v.x + v.y;
    float sq = v.x * v.x + v.y * v.y;
    #pragma unroll
    for (int off = 16; off; off >>= 1) {
        s  += __shfl_xor_sync(0xffffffffu, s,  off);
        sq += __shfl_xor_sync(0xffffffffu, sq, off);
    }
    __shared__ float rs[8], rq[8], stats[2];
    if ((tid & 31) == 0) { rs[tid >> 5] = s; rq[tid >> 5] = sq; }
    __syncthreads();
    if (tid == 0) {
        float S = 0.f, Q = 0.f;
        #pragma unroll
        for (int i = 0; i < 8; i++) { S += rs[i]; Q += rq[i]; }
        float mean = S * (1.0f / ND);
        float var  = Q * (1.0f / ND) - mean * mean;
        stats[0] = mean;
        stats[1] = rsqrtf(var + 1e-5f);
    }
    __syncthreads();
    const float mean = stats[0], inv = stats[1];
    float2 g2 = ((const float2*)gamma)[tid];
    float2 b2 = ((const float2*)beta)[tid];
    float2 o;
    o.x = (v.x - mean) * inv * g2.x + b2.x;
    o.y = (v.y - mean) * inv * g2.y + b2.y;
    ((float2*)(out + (size_t)tok * ND))[tid] = o;
}

// ---------------- fused attention ----------------
__global__ void attn_kernel(const float* __restrict__ rel) {
    const int idx = blockIdx.x;
    const int s = idx & (NS - 1);
    const int h = (idx >> 8) & (NH - 1);
    const int b = idx >> 11;
    const int tid = threadIdx.x;   // 256

    __shared__ float q[HD];
    __shared__ float sc[NS];
    __shared__ float redm[8], reds[8], sval[2];
    __shared__ float pv[4][HD];

    const size_t base = (size_t)(b * NS) * (3 * ND) + h * HD;

    if (tid < HD) q[tid] = g_qkv[base + (size_t)s * (3 * ND) + tid];
    __syncthreads();

    const float* krow = g_qkv + base + ND + (size_t)tid * (3 * ND);
    float dot = 0.f;
    #pragma unroll
    for (int d = 0; d < HD; d += 4) {
        float4 k4 = *(const float4*)(krow + d);
        dot += q[d] * k4.x + q[d + 1] * k4.y + q[d + 2] * k4.z + q[d + 3] * k4.w;
    }
    const float scv = dot * 0.125f + rel[(size_t)s * NS + tid];

    float m = scv;
    #pragma unroll
    for (int off = 16; off; off >>= 1) m = fmaxf(m, __shfl_xor_sync(0xffffffffu, m, off));
    if ((tid & 31) == 0) redm[tid >> 5] = m;
    __syncthreads();
    if (tid == 0) {
        float mm = redm[0];
        #pragma unroll
        for (int i = 1; i < 8; i++) mm = fmaxf(mm, redm[i]);
        sval[0] = mm;
    }
    __syncthreads();

    const float e = expf(scv - sval[0]);
    float ss = e;
    #pragma unroll
    for (int off = 16; off; off >>= 1) ss += __shfl_xor_sync(0xffffffffu, ss, off);
    if ((tid & 31) == 0) reds[tid >> 5] = ss;
    __syncthreads();
    if (tid == 0) {
        float tt = 0.f;
        #pragma unroll
        for (int i = 0; i < 8; i++) tt += reds[i];
        sval[1] = 1.0f / tt;
    }
    __syncthreads();
    sc[tid] = e * sval[1];
    __syncthreads();

    const int g = tid >> 6, d = tid & 63;
    const float* vcol = g_qkv + base + 2 * ND + d;
    float acc = 0.f;
    const int t0 = g * 64;
    #pragma unroll 8
    for (int t = t0; t < t0 + 64; t++) acc += sc[t] * vcol[(size_t)t * (3 * ND)];
    pv[g][d] = acc;
    __syncthreads();
    if (tid < HD) {
        float o = pv[0][tid] + pv[1][tid] + pv[2][tid] + pv[3][tid];
        g_o[(size_t)(b * NS + s) * ND + h * HD + tid] = o;
    }
}

// ---------------- split-bf16 tensor-core GEMM (fp32-accurate) ----------------
// C[M,N] = A[M,K] @ W[N,K]^T + bias (+res) (gelu?)
// x = hi + lo (two bf16). D = Ahi*Bhi + Ahi*Blo + Alo*Bhi (fp32 accum).
// 128x128x16 block tile, 256 threads = 8 warps (2x4), warp tile 64x32,
// mma.sync.m16n8k16.bf16. Smem stores k-PAIRS packed as bf16x2 words:
// layout [kpair][m], stride 136 words (conflict-free: addr%32 = 8*t+g).

__device__ __forceinline__ void split_pack(float a, float b, unsigned& hi, unsigned& lo) {
    __nv_bfloat16 ha = __float2bfloat16_rn(a);
    __nv_bfloat16 hb = __float2bfloat16_rn(b);
    float ra = a - __bfloat162float(ha);
    float rb = b - __bfloat162float(hb);
    __nv_bfloat162 h2 = __halves2bfloat162(ha, hb);           // .x=a (low), .y=b
    __nv_bfloat162 l2 = __floats2bfloat162_rn(ra, rb);
    hi = *(unsigned*)&h2;
    lo = *(unsigned*)&l2;
}

#define MMA_BF16(d, a0,a1,a2,a3, b0,b1)                                         \
    asm volatile("mma.sync.aligned.m16n8k16.row.col.f32.bf16.bf16.f32 "         \
                 "{%0,%1,%2,%3}, {%4,%5,%6,%7}, {%8,%9}, {%0,%1,%2,%3};"        \
                 : "+f"(d[0]), "+f"(d[1]), "+f"(d[2]), "+f"(d[3])               \
                 : "r"(a0), "r"(a1), "r"(a2), "r"(a3), "r"(b0), "r"(b1))

#define SSTRIDE 136

template <bool GELU, bool RES>
__global__ __launch_bounds__(256)
void gemm_bf16x2(const float* __restrict__ A, const float* __restrict__ W,
                 const float* __restrict__ bias, const float* __restrict__ res,
                 float* __restrict__ C, int M, int N, int K) {
    __shared__ unsigned sAhi[8][SSTRIDE];
    __shared__ unsigned sAlo[8][SSTRIDE];
    __shared__ unsigned sWhi[8][SSTRIDE];
    __shared__ unsigned sWlo[8][SSTRIDE];

    const int tid = threadIdx.x;
    const int bm = blockIdx.x * 128;   // M on x (A reuse via L2 for big-N GEMMs)
    const int bn = blockIdx.y * 128;

    const int lr   = tid & 127;        // row within tile for global load
    const int half = tid >> 7;         // 0/1: which 8-k chunk this thread loads
    const int kofs = half * 8;

    const int wid = tid >> 5, lane = tid & 31;
    const int g = lane >> 2, t = lane & 3;
    const int wm = (wid >> 2) * 64;
    const int wn = (wid & 3) * 32;

    float acc[4][4][4];
    #pragma unroll
    for (int i = 0; i < 4; i++)
        #pragma unroll
        for (int j = 0; j < 4; j++)
            #pragma unroll
            for (int c = 0; c < 4; c++) acc[i][j][c] = 0.f;

    const float* aP = A + (size_t)(bm + lr) * K + kofs;
    const float* wP = W + (size_t)(bn + lr) * K + kofs;

    float4 a0v = *(const float4*)(aP);
    float4 a1v = *(const float4*)(aP + 4);
    float4 w0v = *(const float4*)(wP);
    float4 w1v = *(const float4*)(wP + 4);

    for (int k0 = 0; k0 < K; k0 += 16) {
        // stage current tile into smem (split hi/lo, pack k-pairs)
        {
            unsigned h0, l0, h1, l1, h2, l2, h3, l3;
            split_pack(a0v.x, a0v.y, h0, l0);
            split_pack(a0v.z, a0v.w, h1, l1);
            split_pack(a1v.x, a1v.y, h2, l2);
            split_pack(a1v.z, a1v.w, h3, l3);
            const int p = half * 4;
            sAhi[p + 0][lr] = h0; sAlo[p + 0][lr] = l0;
            sAhi[p + 1][lr] = h1; sAlo[p + 1][lr] = l1;
            sAhi[p + 2][lr] = h2; sAlo[p + 2][lr] = l2;
            sAhi[p + 3][lr] = h3; sAlo[p + 3][lr] = l3;
            split_pack(w0v.x, w0v.y, h0, l0);
            split_pack(w0v.z, w0v.w, h1, l1);
            split_pack(w1v.x, w1v.y, h2, l2);
            split_pack(w1v.z, w1v.w, h3, l3);
            sWhi[p + 0][lr] = h0; sWlo[p + 0][lr] = l0;
            sWhi[p + 1][lr] = h1; sWlo[p + 1][lr] = l1;
            sWhi[p + 2][lr] = h2; sWlo[p + 2][lr] = l2;
            sWhi[p + 3][lr] = h3; sWlo[p + 3][lr] = l3;
        }
        __syncthreads();

        if (k0 + 16 < K) {   // prefetch next tile into registers
            a0v = *(const float4*)(aP + k0 + 16);
            a1v = *(const float4*)(aP + k0 + 20);
            w0v = *(const float4*)(wP + k0 + 16);
            w1v = *(const float4*)(wP + k0 + 20);
        }

        // fragments: A hi+lo for all 4 m-frags
        unsigned ah[4][4], al[4][4];
        #pragma unroll
        for (int mf = 0; mf < 4; mf++) {
            const int r0 = wm + mf * 16 + g;
            ah[mf][0] = sAhi[t][r0];     ah[mf][1] = sAhi[t][r0 + 8];
            ah[mf][2] = sAhi[t + 4][r0]; ah[mf][3] = sAhi[t + 4][r0 + 8];
            al[mf][0] = sAlo[t][r0];     al[mf][1] = sAlo[t][r0 + 8];
            al[mf][2] = sAlo[t + 4][r0]; al[mf][3] = sAlo[t + 4][r0 + 8];
        }
        #pragma unroll
        for (int nf = 0; nf < 4; nf++) {
            const int c0 = wn + nf * 8 + g;
            unsigned bh0 = sWhi[t][c0], bh1 = sWhi[t + 4][c0];
            unsigned bl0 = sWlo[t][c0], bl1 = sWlo[t + 4][c0];
            #pragma unroll
            for (int mf = 0; mf < 4; mf++) {
                MMA_BF16(acc[mf][nf], ah[mf][0], ah[mf][1], ah[mf][2], ah[mf][3], bh0, bh1);
                MMA_BF16(acc[mf][nf], ah[mf][0], ah[mf][1], ah[mf][2], ah[mf][3], bl0, bl1);
                MMA_BF16(acc[mf][nf], al[mf][0], al[mf][1], al[mf][2], al[mf][3], bh0, bh1);
            }
        }
        __syncthreads();
    }

    // epilogue (same thread<->element mapping as verified tf32 kernel)
    #pragma unroll
    for (int mf = 0; mf < 4; mf++) {
        const int r0 = bm + wm + mf * 16 + g;
        #pragma unroll
        for (int nf = 0; nf < 4; nf++) {
            const int c0 = bn + wn + nf * 8 + 2 * t;
            const float2 bv = *(const float2*)(bias + c0);
            float v00 = acc[mf][nf][0] + bv.x;
            float v01 = acc[mf][nf][1] + bv.y;
            float v10 = acc[mf][nf][2] + bv.x;
            float v11 = acc[mf][nf][3] + bv.y;
            const size_t i0 = (size_t)r0 * N + c0;
            const size_t i1 = (size_t)(r0 + 8) * N + c0;
            if (RES) {
                const float2 r0v = *(const float2*)(res + i0);
                const float2 r1v = *(const float2*)(res + i1);
                v00 += r0v.x; v01 += r0v.y; v10 += r1v.x; v11 += r1v.y;
            }
            if (GELU) {
                v00 = v00 * 0.5f * (1.0f + erff(v00 * 0.70710678118654752f));
                v01 = v01 * 0.5f * (1.0f + erff(v01 * 0.70710678118654752f));
                v10 = v10 * 0.5f * (1.0f + erff(v10 * 0.70710678118654752f));
                v11 = v11 * 0.5f * (1.0f + erff(v11 * 0.70710678118654752f));
            }
            *(float2*)(C + i0) = make_float2(v00, v01);
            *(float2*)(C + i1) = make_float2(v10, v11);
        }
    }
}

// ---------------- launch ----------------
extern "C" void kernel_launch(void* const* d_in, const int* in_sizes, int n_in,
                              void* d_out, int out_size) {
    const float* patches        = (const float*)d_in[0];
    const float* masked_token   = (const float*)d_in[3];
    const float* partial_params = (const float*)d_in[4];
    const float* emb_w          = (const float*)d_in[5];
    const float* emb_b          = (const float*)d_in[6];
    const float* ln1_g          = (const float*)d_in[7];
    const float* ln1_b          = (const float*)d_in[8];
    const float* in_proj_w      = (const float*)d_in[9];
    const float* in_proj_b      = (const float*)d_in[10];
    const float* out_proj_w     = (const float*)d_in[11];
    const float* out_proj_b     = (const float*)d_in[12];
    const float* rel_pos        = (const float*)d_in[13];
    const float* ln2_g          = (const float*)d_in[14];
    const float* ln2_b          = (const float*)d_in[15];
    const float* ffn_w1         = (const float*)d_in[16];
    const float* ffn_b1         = (const float*)d_in[17];
    const float* ffn_w2         = (const float*)d_in[18];
    const float* ffn_b2         = (const float*)d_in[19];
    const float* outp_w         = (const float*)d_in[20];
    const float* outp_b         = (const float*)d_in[21];
    float* out = (float*)d_out;

    float *x, *xn, *qkv, *o, *h;
    cudaGetSymbolAddress((void**)&x,   g_x);
    cudaGetSymbolAddress((void**)&xn,  g_xn);
    cudaGetSymbolAddress((void**)&qkv, g_qkv);
    cudaGetSymbolAddress((void**)&o,   g_o);
    cudaGetSymbolAddress((void**)&h,   g_h);

    tokenize_embed_kernel<<<NTOK, 128>>>(patches, masked_token, partial_params, emb_w, emb_b);

    for (int l = 0; l < NL; l++) {
        ln_kernel<<<NTOK, 256>>>(x, xn, ln1_g + l * ND, ln1_b + l * ND);

        gemm_bf16x2<false, false><<<dim3(NTOK / 128, 3 * ND / 128), 256>>>(
            xn, in_proj_w + (size_t)l * 3 * ND * ND, in_proj_b + l * 3 * ND,
            nullptr, qkv, NTOK, 3 * ND, ND);

        attn_kernel<<<NB * NH * NS, 256>>>(rel_pos + (size_t)l * NS * NS);

        gemm_bf16x2<false, true><<<dim3(NTOK / 128, ND / 128), 256>>>(
            o, out_proj_w + (size_t)l * ND * ND, out_proj_b + l * ND,
            x, x, NTOK, ND, ND);

        ln_kernel<<<NTOK, 256>>>(x, xn, ln2_g + l * ND, ln2_b + l * ND);

        gemm_bf16x2<true, false><<<dim3(NTOK / 128, NF / 128), 256>>>(
            xn, ffn_w1 + (size_t)l * NF * ND, ffn_b1 + l * NF,
            nullptr, h, NTOK, NF, ND);

        gemm_bf16x2<false, true><<<dim3(NTOK / 128, ND / 128), 256>>>(
            h, ffn_w2 + (size_t)l * ND * NF, ffn_b2 + l * ND,
            x, x, NTOK, ND, NF);
    }

    gemm_bf16x2<false, false><<<dim3(NTOK / 128, NV / 128), 256>>>(
        x, outp_w, outp_b, nullptr, out, NTOK, NV, ND);
}

// round 5
// speedup vs baseline: 1.9800x; 1.9800x over previous
#include <cuda_runtime.h>
#include <cuda_bf16.h>
#include <math.h>
#include <stdint.h>

// ---------------- problem constants ----------------
#define NB   8
#define NS   256
#define NP   16
#define ND   512
#define NH   8
#define HD   64
#define NL   6
#define NF   2048
#define NV   65536
#define NTOK (NB * NS)   // 2048

// ---------------- scratch (device globals; no allocation) ----------------
__device__ float g_x  [NTOK * ND];
__device__ float g_xn [NTOK * ND];
__device__ float g_qkv[NTOK * 3 * ND];
__device__ float g_o  [NTOK * ND];
__device__ float g_h  [NTOK * NF];

__device__ __forceinline__ uint32_t smem_u32(const void* p) {
    uint32_t a;
    asm("{ .reg .u64 t; cvta.to.shared.u64 t, %1; cvt.u32.u64 %0, t; }" : "=r"(a) : "l"(p));
    return a;
}

// ---------------- tokenize + embed ----------------
__global__ void tokenize_embed_kernel(const float* __restrict__ patches,
                                      const float* __restrict__ masked_token,
                                      const float* __restrict__ partial_params,
                                      const float* __restrict__ emb_w,
                                      const float* __restrict__ emb_b) {
    const int tok = blockIdx.x;
    const int tid = threadIdx.x;   // 128 threads
    __shared__ float proc[NP];

    if (tid == 0) {
        const float* f = patches + (size_t)tok * NP;
        bool anyMask = false, anyBin = false;
        int firstBin = -1;
        float fp[NP];
        #pragma unroll
        for (int p = 0; p < NP; p++) {
            float v = f[p];
            fp[p] = v;
            bool m = fabsf(v - 0.5f) < 0.1f;
            if (m) anyMask = true;
            else { anyBin = true; if (firstBin < 0) firstBin = p; }
        }
        if (!anyBin) {
            #pragma unroll
            for (int p = 0; p < NP; p++) proc[p] = masked_token[p];
        } else if (anyMask) {
            int ptok = firstBin * 2 + (int)rintf(fp[firstBin]);
            const float* pp = partial_params + ptok * NP;
            #pragma unroll
            for (int p = 0; p < NP; p++) proc[p] = pp[p];
        } else {
            #pragma unroll
            for (int p = 0; p < NP; p++) proc[p] = fp[p];
        }
    }
    __syncthreads();

    for (int d = tid; d < ND; d += blockDim.x) {
        const float* w = emb_w + d * NP;
        float s = emb_b[d];
        #pragma unroll
        for (int p = 0; p < NP; p++) s += proc[p] * w[p];
        g_x[(size_t)tok * ND + d] = s;
    }
}

// ---------------- layernorm ----------------
__global__ void ln_kernel(const float* __restrict__ in, float* __restrict__ out,
                          const float* __restrict__ gamma, const float* __restrict__ beta) {
    const int tok = blockIdx.x;
    const int tid = threadIdx.x;   // 256
    const float2 v = ((const float2*)(in + (size_t)tok * ND))[tid];

    float s  = v.x + v.y;
    float sq = v.x * v.x + v.y * v.y;
    #pragma unroll
    for (int off = 16; off; off >>= 1) {
        s  += __shfl_xor_sync(0xffffffffu, s,  off);
        sq += __shfl_xor_sync(0xffffffffu, sq, off);
    }
    __shared__ float rs[8], rq[8], stats[2];
    if ((tid & 31) == 0) { rs[tid >> 5] = s; rq[tid >> 5] = sq; }
    __syncthreads();
    if (tid == 0) {
        float S = 0.f, Q = 0.f;
        #pragma unroll
        for (int i = 0; i < 8; i++) { S += rs[i]; Q += rq[i]; }
        float mean = S * (1.0f / ND);
        float var  = Q * (1.0f / ND) - mean * mean;
        stats[0] = mean;
        stats[1] = rsqrtf(var + 1e-5f);
    }
    __syncthreads();
    const float mean = stats[0], inv = stats[1];
    float2 g2 = ((const float2*)gamma)[tid];
    float2 b2 = ((const float2*)beta)[tid];
    float2 o;
    o.x = (v.x - mean) * inv * g2.x + b2.x;
    o.y = (v.y - mean) * inv * g2.y + b2.y;
    ((float2*)(out + (size_t)tok * ND))[tid] = o;
}

// ---------------- fused attention (smem-resident K/V, 1 wave) ----------------
// grid = B*H*2 = 128 blocks, 256 threads (8 warps). Each block handles one
// (b, h) and 128 queries. K stored row-rotated (by 4*(t%16) floats) so the
// per-lane strided reads are bank-conflict free. V, Q plain.
#define ATTN_SMEM (192 * 1024)

__global__ __launch_bounds__(256) void attn_kernel(const float* __restrict__ rel) {
    extern __shared__ float sm[];
    float* Ks = sm;            // [256][64] rotated rows
    float* Vs = sm + 16384;    // [256][64]
    float* Qs = sm + 32768;    // [128][64]
    float* Wb = sm + 40960;    // [8 warps][256][4]

    const int idx = blockIdx.x;
    const int qc = idx & 1;
    const int h  = (idx >> 1) & (NH - 1);
    const int b  = idx >> 4;
    const int tid = threadIdx.x, wid = tid >> 5, L = tid & 31;

    const size_t base = (size_t)(b * NS) * (3 * ND) + h * HD;

    // ---- stage K (rotated), V, Q ----
    {
        const int dc = (tid & 15) * 4;
        int t = tid >> 4;
        #pragma unroll 4
        for (int pass = 0; pass < 16; pass++, t += 16) {
            const float* kR = g_qkv + base + ND + (size_t)t * (3 * ND);
            float4 kv = *(const float4*)(kR + dc);
            const int p = (dc + 4 * (t & 15)) & 63;
            *(float4*)(Ks + t * 64 + p) = kv;
            const float* vR = g_qkv + base + 2 * ND + (size_t)t * (3 * ND);
            *(float4*)(Vs + t * 64 + dc) = *(const float4*)(vR + dc);
        }
        int q = tid >> 4;
        #pragma unroll 4
        for (int pass = 0; pass < 8; pass++, q += 16) {
            const float* qR = g_qkv + base + (size_t)(qc * 128 + q) * (3 * ND);
            *(float4*)(Qs + q * 64 + dc) = *(const float4*)(qR + dc);
        }
    }
    __syncthreads();

    float* wb = Wb + wid * 1024;        // this warp's weight buffer [256][4]
    const int rot = 4 * (L & 15);       // == 4*((L+32j)%16) for all j

    for (int g4 = 0; g4 < 4; g4++) {
        const int q0 = wid * 16 + g4 * 4;      // local query base (0..124)
        const int sRow = qc * 128 + q0;        // sequence position base

        // ---- QK^T: sc[qi][j], lane covers t = L + 32j ----
        float sc[4][8];
        #pragma unroll
        for (int qi = 0; qi < 4; qi++)
            #pragma unroll
            for (int j = 0; j < 8; j++) sc[qi][j] = 0.f;

        #pragma unroll
        for (int dd = 0; dd < 16; dd++) {
            const int d = dd * 4;
            float4 qv[4];
            #pragma unroll
            for (int qi = 0; qi < 4; qi++)
                qv[qi] = *(const float4*)(Qs + (q0 + qi) * 64 + d);
            const int p = (d + rot) & 63;
            #pragma unroll
            for (int j = 0; j < 8; j++) {
                float4 k4 = *(const float4*)(Ks + (L + 32 * j) * 64 + p);
                #pragma unroll
                for (int qi = 0; qi < 4; qi++)
                    sc[qi][j] += qv[qi].x * k4.x + qv[qi].y * k4.y +
                                 qv[qi].z * k4.z + qv[qi].w * k4.w;
            }
        }

        // ---- softmax (scale + rel_pos, max-sub, normalize) ----
        #pragma unroll
        for (int qi = 0; qi < 4; qi++) {
            const float* rrow = rel + (size_t)(sRow + qi) * NS;
            float m = -1e30f;
            #pragma unroll
            for (int j = 0; j < 8; j++) {
                float v = sc[qi][j] * 0.125f + rrow[L + 32 * j];
                sc[qi][j] = v;
                m = fmaxf(m, v);
            }
            #pragma unroll
            for (int off = 16; off; off >>= 1)
                m = fmaxf(m, __shfl_xor_sync(0xffffffffu, m, off));
            float ssum = 0.f;
            #pragma unroll
            for (int j = 0; j < 8; j++) { sc[qi][j] = expf(sc[qi][j] - m); ssum += sc[qi][j]; }
            #pragma unroll
            for (int off = 16; off; off >>= 1)
                ssum += __shfl_xor_sync(0xffffffffu, ssum, off);
            const float inv = 1.0f / ssum;
            #pragma unroll
            for (int j = 0; j < 8; j++) sc[qi][j] *= inv;
        }

        // write weights: wb[t][qi]
        #pragma unroll
        for (int j = 0; j < 8; j++)
            *(float4*)(wb + (L + 32 * j) * 4) =
                make_float4(sc[0][j], sc[1][j], sc[2][j], sc[3][j]);
        __syncwarp();

        // ---- A @ V: lane owns d = 2L, 2L+1 ----
        float2 acc[4];
        #pragma unroll
        for (int qi = 0; qi < 4; qi++) acc[qi] = make_float2(0.f, 0.f);
        #pragma unroll 4
        for (int t = 0; t < NS; t++) {
            float2 v2 = *(const float2*)(Vs + t * 64 + 2 * L);
            float4 w4 = *(const float4*)(wb + t * 4);
            acc[0].x += w4.x * v2.x; acc[0].y += w4.x * v2.y;
            acc[1].x += w4.y * v2.x; acc[1].y += w4.y * v2.y;
            acc[2].x += w4.z * v2.x; acc[2].y += w4.z * v2.y;
            acc[3].x += w4.w * v2.x; acc[3].y += w4.w * v2.y;
        }
        #pragma unroll
        for (int qi = 0; qi < 4; qi++)
            *(float2*)(g_o + (size_t)(b * NS + sRow + qi) * ND + h * HD + 2 * L) = acc[qi];
        __syncwarp();
    }
}

// ---------------- split-bf16 mma.sync GEMM with ldmatrix ----------------
// C[M,N] = A[M,K] @ W[N,K]^T + bias (+res) (gelu?)
// 3-term split: D = Ahi*Whi + Ahi*Wlo + Alo*Whi, fp32 accumulate.
// CTA tile TM x 128, k16 stages, double-buffered smem, 8 warps (2x4),
// warp tile (TM/2) x 32. Smem layout: per tile [m][16B k-chunk] with
// chunk swizzle kc' = kc ^ ((m>>2)&1)  (conflict-free STS + LDSM).

__device__ __forceinline__ void split_pack(float a, float b, unsigned& hi, unsigned& lo) {
    __nv_bfloat16 ha = __float2bfloat16_rn(a);
    __nv_bfloat16 hb = __float2bfloat16_rn(b);
    float ra = a - __bfloat162float(ha);
    float rb = b - __bfloat162float(hb);
    __nv_bfloat162 h2 = __halves2bfloat162(ha, hb);
    __nv_bfloat162 l2 = __floats2bfloat162_rn(ra, rb);
    hi = *(unsigned*)&h2;
    lo = *(unsigned*)&l2;
}

__device__ __forceinline__ void pack8(float4 v0, float4 v1, uint4& hi, uint4& lo) {
    split_pack(v0.x, v0.y, hi.x, lo.x);
    split_pack(v0.z, v0.w, hi.y, lo.y);
    split_pack(v1.x, v1.y, hi.z, lo.z);
    split_pack(v1.z, v1.w, hi.w, lo.w);
}

#define MMA_BF16(d, a0,a1,a2,a3, b0,b1)                                         \
    asm volatile("mma.sync.aligned.m16n8k16.row.col.f32.bf16.bf16.f32 "         \
                 "{%0,%1,%2,%3}, {%4,%5,%6,%7}, {%8,%9}, {%0,%1,%2,%3};"        \
                 : "+f"(d[0]), "+f"(d[1]), "+f"(d[2]), "+f"(d[3])               \
                 : "r"(a0), "r"(a1), "r"(a2), "r"(a3), "r"(b0), "r"(b1))

#define LDSM4(r, addr)                                                          \
    asm volatile("ldmatrix.sync.aligned.m8n8.x4.shared.b16 {%0,%1,%2,%3}, [%4];"\
                 : "=r"((r)[0]), "=r"((r)[1]), "=r"((r)[2]), "=r"((r)[3])       \
                 : "r"(addr))

__device__ __forceinline__ uint32_t chunk_off(int m, int kc) {
    return (uint32_t)(m * 32 + ((kc ^ ((m >> 2) & 1)) << 4));
}

template <int TM, bool GELU, bool RES>
__global__ __launch_bounds__(256)
void gemm_lds(const float* __restrict__ A, const float* __restrict__ W,
              const float* __restrict__ bias, const float* __restrict__ res,
              float* __restrict__ C, int M, int N, int K) {
    constexpr int MF      = TM / 32;            // A frags per warp (2 or 4)
    constexpr int OFF_AH  = 0;
    constexpr int OFF_AL  = TM * 32;
    constexpr int OFF_WH  = 2 * TM * 32;
    constexpr int OFF_WL  = 2 * TM * 32 + 4096;
    constexpr int STAGE_B = 2 * TM * 32 + 8192;

    __shared__ char smem[2 * STAGE_B];
    const uint32_t sb = smem_u32(smem);

    const int tid = threadIdx.x;
    const int bm = blockIdx.x * TM;
    const int bn = blockIdx.y * 128;

    const int wid = tid >> 5, lane = tid & 31;
    const int g = lane >> 2, t4 = lane & 3;
    const int wm = (wid >> 2) * (TM / 2);
    const int wn = (wid & 3) * 32;

    // loader roles
    const bool aAct = (TM == 128) || (tid < 128);
    const int  ar   = (tid >> 1) & (TM - 1);
    const int  ah   = tid & 1;
    const int  wr   = tid >> 1;
    const int  wh   = tid & 1;
    const uint32_t chA = chunk_off(ar, ah);
    const uint32_t chW = chunk_off(wr, wh);

    // ldmatrix fragment addresses (buffer 0)
    const int sel = lane >> 3, ri = lane & 7;
    uint32_t aAdH[MF], aAdL[MF], bAdH[2], bAdL[2];
    #pragma unroll
    for (int mf = 0; mf < MF; mf++) {
        const int m = wm + mf * 16 + (sel & 1) * 8 + ri;
        const int kc = sel >> 1;
        const uint32_t ch = chunk_off(m, kc);
        aAdH[mf] = sb + OFF_AH + ch;
        aAdL[mf] = sb + OFF_AL + ch;
    }
    #pragma unroll
    for (int p = 0; p < 2; p++) {
        const int n = wn + p * 16 + (sel >> 1) * 8 + ri;
        const int kc = sel & 1;
        const uint32_t ch = chunk_off(n, kc);
        bAdH[p] = sb + OFF_WH + ch;
        bAdL[p] = sb + OFF_WL + ch;
    }

    float acc[MF][4][4];
    #pragma unroll
    for (int i = 0; i < MF; i++)
        #pragma unroll
        for (int j = 0; j < 4; j++)
            #pragma unroll
            for (int c = 0; c < 4; c++) acc[i][j][c] = 0.f;

    const float* aP = A + (size_t)(bm + ar) * K + ah * 8;
    const float* wP = W + (size_t)(bn + wr) * K + wh * 8;

    const int S = K / 16;
    float4 a0, a1, w0, w1;

    // prologue: stage 0
    if (aAct) { a0 = *(const float4*)(aP); a1 = *(const float4*)(aP + 4); }
    w0 = *(const float4*)(wP); w1 = *(const float4*)(wP + 4);
    {
        uint4 hi, lo;
        if (aAct) {
            pack8(a0, a1, hi, lo);
            *(uint4*)(smem + OFF_AH + chA) = hi;
            *(uint4*)(smem + OFF_AL + chA) = lo;
        }
        pack8(w0, w1, hi, lo);
        *(uint4*)(smem + OFF_WH + chW) = hi;
        *(uint4*)(smem + OFF_WL + chW) = lo;
    }
    __syncthreads();

    for (int s = 0; s < S; s++) {
        const int k0 = (s + 1) * 16;
        if (s + 1 < S) {
            if (aAct) { a0 = *(const float4*)(aP + k0); a1 = *(const float4*)(aP + k0 + 4); }
            w0 = *(const float4*)(wP + k0); w1 = *(const float4*)(wP + k0 + 4);
        }

        // ---- compute from buffer s&1 ----
        const uint32_t off = (uint32_t)((s & 1) * STAGE_B);
        uint32_t aH[MF][4], aL[MF][4], bH[2][4], bL[2][4];
        #pragma unroll
        for (int mf = 0; mf < MF; mf++) {
            LDSM4(aH[mf], aAdH[mf] + off);
            LDSM4(aL[mf], aAdL[mf] + off);
        }
        #pragma unroll
        for (int p = 0; p < 2; p++) {
            LDSM4(bH[p], bAdH[p] + off);
            LDSM4(bL[p], bAdL[p] + off);
        }
        #pragma unroll
        for (int mf = 0; mf < MF; mf++)
            #pragma unroll
            for (int nf = 0; nf < 4; nf++) {
                const int p = nf >> 1, q = (nf & 1) * 2;
                MMA_BF16(acc[mf][nf], aH[mf][0], aH[mf][1], aH[mf][2], aH[mf][3],
                         bH[p][q], bH[p][q + 1]);
                MMA_BF16(acc[mf][nf], aH[mf][0], aH[mf][1], aH[mf][2], aH[mf][3],
                         bL[p][q], bL[p][q + 1]);
                MMA_BF16(acc[mf][nf], aL[mf][0], aL[mf][1], aL[mf][2], aL[mf][3],
                         bH[p][q], bH[p][q + 1]);
            }

        // ---- stage s+1 into other buffer ----
        if (s + 1 < S) {
            char* dst = smem + ((s + 1) & 1) * STAGE_B;
            uint4 hi, lo;
            if (aAct) {
                pack8(a0, a1, hi, lo);
                *(uint4*)(dst + OFF_AH + chA) = hi;
                *(uint4*)(dst + OFF_AL + chA) = lo;
            }
            pack8(w0, w1, hi, lo);
            *(uint4*)(dst + OFF_WH + chW) = hi;
            *(uint4*)(dst + OFF_WL + chW) = lo;
        }
        __syncthreads();
    }

    // ---- epilogue (fragment layout: row g/g+8, cols 2*t4, 2*t4+1) ----
    #pragma unroll
    for (int mf = 0; mf < MF; mf++) {
        const int r0 = bm + wm + mf * 16 + g;
        #pragma unroll
        for (int nf = 0; nf < 4; nf++) {
            const int c0 = bn + wn + nf * 8 + 2 * t4;
            const float2 bv = *(const float2*)(bias + c0);
            float v00 = acc[mf][nf][0] + bv.x;
            float v01 = acc[mf][nf][1] + bv.y;
            float v10 = acc[mf][nf][2] + bv.x;
            float v11 = acc[mf][nf][3] + bv.y;
            const size_t i0 = (size_t)r0 * N + c0;
            const size_t i1 = (size_t)(r0 + 8) * N + c0;
            if (RES) {
                const float2 r0v = *(const float2*)(res + i0);
                const float2 r1v = *(const float2*)(res + i1);
                v00 += r0v.x; v01 += r0v.y; v10 += r1v.x; v11 += r1v.y;
            }
            if (GELU) {
                v00 = v00 * 0.5f * (1.0f + erff(v00 * 0.70710678118654752f));
                v01 = v01 * 0.5f * (1.0f + erff(v01 * 0.70710678118654752f));
                v10 = v10 * 0.5f * (1.0f + erff(v10 * 0.70710678118654752f));
                v11 = v11 * 0.5f * (1.0f + erff(v11 * 0.70710678118654752f));
            }
            *(float2*)(C + i0) = make_float2(v00, v01);
            *(float2*)(C + i1) = make_float2(v10, v11);
        }
    }
}

// ---------------- launch ----------------
extern "C" void kernel_launch(void* const* d_in, const int* in_sizes, int n_in,
                              void* d_out, int out_size) {
    const float* patches        = (const float*)d_in[0];
    const float* masked_token   = (const float*)d_in[3];
    const float* partial_params = (const float*)d_in[4];
    const float* emb_w          = (const float*)d_in[5];
    const float* emb_b          = (const float*)d_in[6];
    const float* ln1_g          = (const float*)d_in[7];
    const float* ln1_b          = (const float*)d_in[8];
    const float* in_proj_w      = (const float*)d_in[9];
    const float* in_proj_b      = (const float*)d_in[10];
    const float* out_proj_w     = (const float*)d_in[11];
    const float* out_proj_b     = (const float*)d_in[12];
    const float* rel_pos        = (const float*)d_in[13];
    const float* ln2_g          = (const float*)d_in[14];
    const float* ln2_b          = (const float*)d_in[15];
    const float* ffn_w1         = (const float*)d_in[16];
    const float* ffn_b1         = (const float*)d_in[17];
    const float* ffn_w2         = (const float*)d_in[18];
    const float* ffn_b2         = (const float*)d_in[19];
    const float* outp_w         = (const float*)d_in[20];
    const float* outp_b         = (const float*)d_in[21];
    float* out = (float*)d_out;

    float *x, *xn, *qkv, *o, *h;
    cudaGetSymbolAddress((void**)&x,   g_x);
    cudaGetSymbolAddress((void**)&xn,  g_xn);
    cudaGetSymbolAddress((void**)&qkv, g_qkv);
    cudaGetSymbolAddress((void**)&o,   g_o);
    cudaGetSymbolAddress((void**)&h,   g_h);

    cudaFuncSetAttribute(attn_kernel, cudaFuncAttributeMaxDynamicSharedMemorySize, ATTN_SMEM);

    tokenize_embed_kernel<<<NTOK, 128>>>(patches, masked_token, partial_params, emb_w, emb_b);

    for (int l = 0; l < NL; l++) {
        ln_kernel<<<NTOK, 256>>>(x, xn, ln1_g + l * ND, ln1_b + l * ND);

        gemm_lds<64, false, false><<<dim3(NTOK / 64, 3 * ND / 128), 256>>>(
            xn, in_proj_w + (size_t)l * 3 * ND * ND, in_proj_b + l * 3 * ND,
            nullptr, qkv, NTOK, 3 * ND, ND);

        attn_kernel<<<NB * NH * 2, 256, ATTN_SMEM>>>(rel_pos + (size_t)l * NS * NS);

        gemm_lds<64, false, true><<<dim3(NTOK / 64, ND / 128), 256>>>(
            o, out_proj_w + (size_t)l * ND * ND, out_proj_b + l * ND,
            x, x, NTOK, ND, ND);

        ln_kernel<<<NTOK, 256>>>(x, xn, ln2_g + l * ND, ln2_b + l * ND);

        gemm_lds<128, true, false><<<dim3(NTOK / 128, NF / 128), 256>>>(
            xn, ffn_w1 + (size_t)l * NF * ND, ffn_b1 + l * NF,
            nullptr, h, NTOK, NF, ND);

        gemm_lds<64, false, true><<<dim3(NTOK / 64, ND / 128), 256>>>(
            h, ffn_w2 + (size_t)l * ND * NF, ffn_b2 + l * ND,
            x, x, NTOK, ND, NF);
    }

    gemm_lds<128, false, false><<<dim3(NTOK / 128, NV / 128), 256>>>(
        x, outp_w, outp_b, nullptr, out, NTOK, NV, ND);
}

// round 6
// speedup vs baseline: 3.2675x; 1.6502x over previous
#include <cuda_runtime.h>
#include <cuda_bf16.h>
#include <math.h>
#include <stdint.h>

// ---------------- problem constants ----------------
#define NB   8
#define NS   256
#define NP   16
#define ND   512
#define NH   8
#define HD   64
#define NL   6
#define NF   2048
#define NV   65536
#define NTOK (NB * NS)   // 2048

// ---------------- scratch (device globals; no allocation) ----------------
__device__ float g_x  [NTOK * ND];          // residual stream (fp32)
__device__ float g_qkv[NTOK * 3 * ND];      // qkv projection (fp32)

// split-bf16 tile buffers (hi|lo 2KB blocks of 64 rows x 16 k, swizzled)
__device__ uint8_t s_xn [NTOK * ND * 4];          // LN output
__device__ uint8_t s_o  [NTOK * ND * 4];          // attention output
__device__ uint8_t s_h  [NTOK * NF * 4];          // FFN1 output
__device__ uint8_t s_xf [NTOK * ND * 4];          // final residual
__device__ uint8_t s_win[NL * 3 * ND * ND * 4];   // in_proj weights
__device__ uint8_t s_wo [NL * ND * ND * 4];       // out_proj
__device__ uint8_t s_w1 [NL * NF * ND * 4];       // ffn_w1
__device__ uint8_t s_w2 [(size_t)NL * ND * NF * 4]; // ffn_w2
__device__ uint8_t s_wv [(size_t)NV * ND * 4];    // outp_w (134 MB)

__device__ __forceinline__ uint32_t smem_u32(const void* p) {
    uint32_t a;
    asm("{ .reg .u64 t; cvta.to.shared.u64 t, %1; cvt.u32.u64 %0, t; }" : "=r"(a) : "l"(p));
    return a;
}

// ---------------- split helpers ----------------
__device__ __forceinline__ void split_pack(float a, float b, unsigned& hi, unsigned& lo) {
    __nv_bfloat16 ha = __float2bfloat16_rn(a);
    __nv_bfloat16 hb = __float2bfloat16_rn(b);
    float ra = a - __bfloat162float(ha);
    float rb = b - __bfloat162float(hb);
    __nv_bfloat162 h2 = __halves2bfloat162(ha, hb);
    __nv_bfloat162 l2 = __floats2bfloat162_rn(ra, rb);
    hi = *(unsigned*)&h2;
    lo = *(unsigned*)&l2;
}
__device__ __forceinline__ void pack8(float4 v0, float4 v1, uint4& hi, uint4& lo) {
    split_pack(v0.x, v0.y, hi.x, lo.x);
    split_pack(v0.z, v0.w, hi.y, lo.y);
    split_pack(v1.x, v1.y, hi.z, lo.z);
    split_pack(v1.z, v1.w, hi.w, lo.w);
}
// store 2 adjacent elements (col even) into split tile format
__device__ __forceinline__ void store_split2(uint8_t* base, int K, int row, int col,
                                             float a, float b) {
    unsigned hi, lo;
    split_pack(a, b, hi, lo);
    size_t blk = (size_t)(row >> 6) * (K >> 4) + (col >> 4);
    uint32_t off = (uint32_t)((row & 63) * 32 +
                   ((((col >> 3) & 1) ^ ((row >> 2) & 1)) << 4) + (col & 7) * 2);
    *(unsigned*)(base + blk * 4096 + off) = hi;
    *(unsigned*)(base + blk * 4096 + 2048 + off) = lo;
}

// ---------------- weight conversion (fp32 [R,K] -> split tiles) ----------------
__global__ void convert_w(const float* __restrict__ src, uint8_t* __restrict__ dst,
                          int K, int nChunks) {
    int ct = blockIdx.x * 256 + threadIdx.x;
    if (ct >= nChunks) return;
    int within = ct & 127;
    int blk = ct >> 7;
    int r = within >> 1, kc = within & 1;
    int stages = K >> 4;
    int rt = blk / stages, s = blk - rt * stages;
    const float* p = src + (size_t)(rt * 64 + r) * K + s * 16 + kc * 8;
    float4 v0 = *(const float4*)p, v1 = *(const float4*)(p + 4);
    uint4 hi, lo;
    pack8(v0, v1, hi, lo);
    uint32_t off = (uint32_t)(r * 32 + ((kc ^ ((r >> 2) & 1)) << 4));
    *(uint4*)(dst + (size_t)blk * 4096 + off) = hi;
    *(uint4*)(dst + (size_t)blk * 4096 + 2048 + off) = lo;
}

// convert fp32 activations [rows x 512] to split tiles
__global__ void convert_x_kernel(const float* __restrict__ src, uint8_t* __restrict__ dst) {
    const int row = blockIdx.x;
    const int d = threadIdx.x * 2;
    float2 v = ((const float2*)(src + (size_t)row * ND))[threadIdx.x];
    store_split2(dst, ND, row, d, v.x, v.y);
}

// ---------------- tokenize + embed ----------------
__global__ void tokenize_embed_kernel(const float* __restrict__ patches,
                                      const float* __restrict__ masked_token,
                                      const float* __restrict__ partial_params,
                                      const float* __restrict__ emb_w,
                                      const float* __restrict__ emb_b) {
    const int tok = blockIdx.x;
    const int tid = threadIdx.x;   // 128 threads
    __shared__ float proc[NP];

    if (tid == 0) {
        const float* f = patches + (size_t)tok * NP;
        bool anyMask = false, anyBin = false;
        int firstBin = -1;
        float fp[NP];
        #pragma unroll
        for (int p = 0; p < NP; p++) {
            float v = f[p];
            fp[p] = v;
            bool m = fabsf(v - 0.5f) < 0.1f;
            if (m) anyMask = true;
            else { anyBin = true; if (firstBin < 0) firstBin = p; }
        }
        if (!anyBin) {
            #pragma unroll
            for (int p = 0; p < NP; p++) proc[p] = masked_token[p];
        } else if (anyMask) {
            int ptok = firstBin * 2 + (int)rintf(fp[firstBin]);
            const float* pp = partial_params + ptok * NP;
            #pragma unroll
            for (int p = 0; p < NP; p++) proc[p] = pp[p];
        } else {
            #pragma unroll
            for (int p = 0; p < NP; p++) proc[p] = fp[p];
        }
    }
    __syncthreads();

    for (int d = tid; d < ND; d += blockDim.x) {
        const float* w = emb_w + d * NP;
        float s = emb_b[d];
        #pragma unroll
        for (int p = 0; p < NP; p++) s += proc[p] * w[p];
        g_x[(size_t)tok * ND + d] = s;
    }
}

// ---------------- layernorm (fp32 in -> split-bf16 tile out) ----------------
__global__ void ln_kernel(const float* __restrict__ in, uint8_t* __restrict__ out,
                          const float* __restrict__ gamma, const float* __restrict__ beta) {
    const int tok = blockIdx.x;
    const int tid = threadIdx.x;   // 256
    const float2 v = ((const float2*)(in + (size_t)tok * ND))[tid];

    float s  = v.x + v.y;
    float sq = v.x * v.x + v.y * v.y;
    #pragma unroll
    for (int off = 16; off; off >>= 1) {
        s  += __shfl_xor_sync(0xffffffffu, s,  off);
        sq += __shfl_xor_sync(0xffffffffu, sq, off);
    }
    __shared__ float rs[8], rq[8], stats[2];
    if ((tid & 31) == 0) { rs[tid >> 5] = s; rq[tid >> 5] = sq; }
    __syncthreads();
    if (tid == 0) {
        float S = 0.f, Q = 0.f;
        #pragma unroll
        for (int i = 0; i < 8; i++) { S += rs[i]; Q += rq[i]; }
        float mean = S * (1.0f / ND);
        float var  = Q * (1.0f / ND) - mean * mean;
        stats[0] = mean;
        stats[1] = rsqrtf(var + 1e-5f);
    }
    __syncthreads();
    const float mean = stats[0], inv = stats[1];
    float2 g2 = ((const float2*)gamma)[tid];
    float2 b2 = ((const float2*)beta)[tid];
    float ox = (v.x - mean) * inv * g2.x + b2.x;
    float oy = (v.y - mean) * inv * g2.y + b2.y;
    store_split2(out, ND, tok, tid * 2, ox, oy);
}

// ---------------- fused attention (smem K/V, split output) ----------------
#define ATTN_SMEM (192 * 1024)

__global__ __launch_bounds__(256) void attn_kernel(const float* __restrict__ rel) {
    extern __shared__ float sm[];
    float* Ks = sm;            // [256][64] rotated rows
    float* Vs = sm + 16384;    // [256][64]
    float* Qs = sm + 32768;    // [128][64]
    float* Wb = sm + 40960;    // [8 warps][256][4]

    const int idx = blockIdx.x;
    const int qc = idx & 1;
    const int h  = (idx >> 1) & (NH - 1);
    const int b  = idx >> 4;
    const int tid = threadIdx.x, wid = tid >> 5, L = tid & 31;

    const size_t base = (size_t)(b * NS) * (3 * ND) + h * HD;

    {
        const int dc = (tid & 15) * 4;
        int t = tid >> 4;
        #pragma unroll 4
        for (int pass = 0; pass < 16; pass++, t += 16) {
            const float* kR = g_qkv + base + ND + (size_t)t * (3 * ND);
            float4 kv = *(const float4*)(kR + dc);
            const int p = (dc + 4 * (t & 15)) & 63;
            *(float4*)(Ks + t * 64 + p) = kv;
            const float* vR = g_qkv + base + 2 * ND + (size_t)t * (3 * ND);
            *(float4*)(Vs + t * 64 + dc) = *(const float4*)(vR + dc);
        }
        int q = tid >> 4;
        #pragma unroll 4
        for (int pass = 0; pass < 8; pass++, q += 16) {
            const float* qR = g_qkv + base + (size_t)(qc * 128 + q) * (3 * ND);
            *(float4*)(Qs + q * 64 + dc) = *(const float4*)(qR + dc);
        }
    }
    __syncthreads();

    float* wb = Wb + wid * 1024;
    const int rot = 4 * (L & 15);

    for (int g4 = 0; g4 < 4; g4++) {
        const int q0 = wid * 16 + g4 * 4;
        const int sRow = qc * 128 + q0;

        float sc[4][8];
        #pragma unroll
        for (int qi = 0; qi < 4; qi++)
            #pragma unroll
            for (int j = 0; j < 8; j++) sc[qi][j] = 0.f;

        #pragma unroll
        for (int dd = 0; dd < 16; dd++) {
            const int d = dd * 4;
            float4 qv[4];
            #pragma unroll
            for (int qi = 0; qi < 4; qi++)
                qv[qi] = *(const float4*)(Qs + (q0 + qi) * 64 + d);
            const int p = (d + rot) & 63;
            #pragma unroll
            for (int j = 0; j < 8; j++) {
                float4 k4 = *(const float4*)(Ks + (L + 32 * j) * 64 + p);
                #pragma unroll
                for (int qi = 0; qi < 4; qi++)
                    sc[qi][j] += qv[qi].x * k4.x + qv[qi].y * k4.y +
                                 qv[qi].z * k4.z + qv[qi].w * k4.w;
            }
        }

        #pragma unroll
        for (int qi = 0; qi < 4; qi++) {
            const float* rrow = rel + (size_t)(sRow + qi) * NS;
            float m = -1e30f;
            #pragma unroll
            for (int j = 0; j < 8; j++) {
                float v = sc[qi][j] * 0.125f + rrow[L + 32 * j];
                sc[qi][j] = v;
                m = fmaxf(m, v);
            }
            #pragma unroll
            for (int off = 16; off; off >>= 1)
                m = fmaxf(m, __shfl_xor_sync(0xffffffffu, m, off));
            float ssum = 0.f;
            #pragma unroll
            for (int j = 0; j < 8; j++) { sc[qi][j] = expf(sc[qi][j] - m); ssum += sc[qi][j]; }
            #pragma unroll
            for (int off = 16; off; off >>= 1)
                ssum += __shfl_xor_sync(0xffffffffu, ssum, off);
            const float inv = 1.0f / ssum;
            #pragma unroll
            for (int j = 0; j < 8; j++) sc[qi][j] *= inv;
        }

        #pragma unroll
        for (int j = 0; j < 8; j++)
            *(float4*)(wb + (L + 32 * j) * 4) =
                make_float4(sc[0][j], sc[1][j], sc[2][j], sc[3][j]);
        __syncwarp();

        float2 acc[4];
        #pragma unroll
        for (int qi = 0; qi < 4; qi++) acc[qi] = make_float2(0.f, 0.f);
        #pragma unroll 4
        for (int t = 0; t < NS; t++) {
            float2 v2 = *(const float2*)(Vs + t * 64 + 2 * L);
            float4 w4 = *(const float4*)(wb + t * 4);
            acc[0].x += w4.x * v2.x; acc[0].y += w4.x * v2.y;
            acc[1].x += w4.y * v2.x; acc[1].y += w4.y * v2.y;
            acc[2].x += w4.z * v2.x; acc[2].y += w4.z * v2.y;
            acc[3].x += w4.w * v2.x; acc[3].y += w4.w * v2.y;
        }
        #pragma unroll
        for (int qi = 0; qi < 4; qi++)
            store_split2(s_o, ND, b * NS + sRow + qi, h * HD + 2 * L,
                         acc[qi].x, acc[qi].y);
        __syncwarp();
    }
}

// ---------------- split-bf16 GEMM: cp.async pipeline + ldmatrix + mma ----------
// A, W pre-split into tile format. 3-term: AhWh + AhWl + AlWh, fp32 accum.
// EPI: 0 = fp32+bias, 1 = fp32+bias+res, 2 = split-gelu output.

#define MMA_BF16(d, a0,a1,a2,a3, b0,b1)                                         \
    asm volatile("mma.sync.aligned.m16n8k16.row.col.f32.bf16.bf16.f32 "         \
                 "{%0,%1,%2,%3}, {%4,%5,%6,%7}, {%8,%9}, {%0,%1,%2,%3};"        \
                 : "+f"(d[0]), "+f"(d[1]), "+f"(d[2]), "+f"(d[3])               \
                 : "r"(a0), "r"(a1), "r"(a2), "r"(a3), "r"(b0), "r"(b1))

#define LDSM4(r, addr)                                                          \
    asm volatile("ldmatrix.sync.aligned.m8n8.x4.shared.b16 {%0,%1,%2,%3}, [%4];"\
                 : "=r"((r)[0]), "=r"((r)[1]), "=r"((r)[2]), "=r"((r)[3])       \
                 : "r"(addr))

#define CP16(dst, src)                                                          \
    asm volatile("cp.async.cg.shared.global [%0], [%1], 16;" :: "r"(dst), "l"(src))
#define CP_COMMIT() asm volatile("cp.async.commit_group;" ::: "memory")
#define CP_WAIT2()  asm volatile("cp.async.wait_group 2;" ::: "memory")

__device__ __forceinline__ uint32_t tile_off(int m, int kc) {
    return (uint32_t)((m >> 6) * 4096 + (m & 63) * 32 +
                      ((kc ^ ((m >> 2) & 1)) << 4));
}

template <int TM, int EPI>
__global__ __launch_bounds__(256)
void gemm_split(const uint8_t* __restrict__ A, const uint8_t* __restrict__ W,
                const float* __restrict__ bias, const float* __restrict__ res,
                void* __restrict__ Cout, int M, int N, int K) {
    constexpr int NREG  = TM / 64 + 2;           // 4096B regions per stage
    constexpr int ST    = NREG * 4096;           // stage bytes
    constexpr int AWOFF = (TM / 64) * 4096;      // W offset within stage
    constexpr int MF    = TM / 32;
    constexpr int NSTG  = 4;

    extern __shared__ uint8_t smem[];
    const uint32_t sb = smem_u32(smem);

    const int tid = threadIdx.x;
    const int bm = blockIdx.x * TM;
    const int bn = blockIdx.y * 128;
    const int wid = tid >> 5, lane = tid & 31;
    const int g = lane >> 2, t4 = lane & 3;
    const int wm = (wid >> 2) * (TM / 2);
    const int wn = (wid & 3) * 32;

    const int S = K >> 4;

    // per-stage source pointers (advance 4096B per stage)
    const uint8_t* ps[NREG];
    {
        const int mt0 = blockIdx.x * (TM / 64);
        const int nt0 = blockIdx.y * 2;
        #pragma unroll
        for (int i = 0; i < TM / 64; i++)
            ps[i] = A + (size_t)(mt0 + i) * S * 4096;
        ps[TM / 64]     = W + (size_t)nt0 * S * 4096;
        ps[TM / 64 + 1] = W + (size_t)(nt0 + 1) * S * 4096;
    }

    // ldmatrix fragment offsets within a stage
    const int sel = lane >> 3, ri = lane & 7;
    uint32_t aOffH[MF], bOffH[2];
    #pragma unroll
    for (int mf = 0; mf < MF; mf++) {
        const int m = wm + mf * 16 + (sel & 1) * 8 + ri;
        aOffH[mf] = tile_off(m, sel >> 1);
    }
    #pragma unroll
    for (int p = 0; p < 2; p++) {
        const int n = wn + p * 16 + (sel >> 1) * 8 + ri;
        bOffH[p] = AWOFF + tile_off(n, sel & 1);
    }

    float acc[MF][4][4];
    #pragma unroll
    for (int i = 0; i < MF; i++)
        #pragma unroll
        for (int j = 0; j < 4; j++)
            #pragma unroll
            for (int c = 0; c < 4; c++) acc[i][j][c] = 0.f;

    // prologue: issue first NSTG-1 stages
    #pragma unroll
    for (int s = 0; s < NSTG - 1; s++) {
        const uint32_t dst = sb + s * ST + tid * 16;
        #pragma unroll
        for (int c = 0; c < NREG; c++)
            CP16(dst + c * 4096, ps[c] + tid * 16);
        #pragma unroll
        for (int c = 0; c < NREG; c++) ps[c] += 4096;
        CP_COMMIT();
    }

    for (int s = 0; s < S; s++) {
        CP_WAIT2();
        __syncthreads();

        const uint32_t stg = sb + (uint32_t)((s & 3) * ST);
        uint32_t aH[MF][4], aL[MF][4], bH[2][4], bL[2][4];
        #pragma unroll
        for (int mf = 0; mf < MF; mf++) {
            LDSM4(aH[mf], stg + aOffH[mf]);
            LDSM4(aL[mf], stg + aOffH[mf] + 2048);
        }
        #pragma unroll
        for (int p = 0; p < 2; p++) {
            LDSM4(bH[p], stg + bOffH[p]);
            LDSM4(bL[p], stg + bOffH[p] + 2048);
        }
        #pragma unroll
        for (int mf = 0; mf < MF; mf++)
            #pragma unroll
            for (int nf = 0; nf < 4; nf++) {
                const int p = nf >> 1, q = (nf & 1) * 2;
                MMA_BF16(acc[mf][nf], aH[mf][0], aH[mf][1], aH[mf][2], aH[mf][3],
                         bH[p][q], bH[p][q + 1]);
                MMA_BF16(acc[mf][nf], aH[mf][0], aH[mf][1], aH[mf][2], aH[mf][3],
                         bL[p][q], bL[p][q + 1]);
                MMA_BF16(acc[mf][nf], aL[mf][0], aL[mf][1], aL[mf][2], aL[mf][3],
                         bH[p][q], bH[p][q + 1]);
            }

        if (s + NSTG - 1 < S) {
            const uint32_t dst = sb + (uint32_t)(((s + NSTG - 1) & 3) * ST) + tid * 16;
            #pragma unroll
            for (int c = 0; c < NREG; c++)
                CP16(dst + c * 4096, ps[c] + tid * 16);
            #pragma unroll
            for (int c = 0; c < NREG; c++) ps[c] += 4096;
        }
        CP_COMMIT();
    }

    // ---- epilogue ----
    #pragma unroll
    for (int mf = 0; mf < MF; mf++) {
        const int r0 = bm + wm + mf * 16 + g;
        #pragma unroll
        for (int nf = 0; nf < 4; nf++) {
            const int c0 = bn + wn + nf * 8 + 2 * t4;
            const float2 bv = *(const float2*)(bias + c0);
            float v00 = acc[mf][nf][0] + bv.x;
            float v01 = acc[mf][nf][1] + bv.y;
            float v10 = acc[mf][nf][2] + bv.x;
            float v11 = acc[mf][nf][3] + bv.y;
            if (EPI == 2) {
                v00 = v00 * 0.5f * (1.0f + erff(v00 * 0.70710678118654752f));
                v01 = v01 * 0.5f * (1.0f + erff(v01 * 0.70710678118654752f));
                v10 = v10 * 0.5f * (1.0f + erff(v10 * 0.70710678118654752f));
                v11 = v11 * 0.5f * (1.0f + erff(v11 * 0.70710678118654752f));
                uint8_t* C = (uint8_t*)Cout;
                store_split2(C, N, r0,     c0, v00, v01);
                store_split2(C, N, r0 + 8, c0, v10, v11);
            } else {
                float* C = (float*)Cout;
                const size_t i0 = (size_t)r0 * N + c0;
                const size_t i1 = (size_t)(r0 + 8) * N + c0;
                if (EPI == 1) {
                    const float2 r0v = *(const float2*)(res + i0);
                    const float2 r1v = *(const float2*)(res + i1);
                    v00 += r0v.x; v01 += r0v.y; v10 += r1v.x; v11 += r1v.y;
                }
                *(float2*)(C + i0) = make_float2(v00, v01);
                *(float2*)(C + i1) = make_float2(v10, v11);
            }
        }
    }
}

// ---------------- launch ----------------
extern "C" void kernel_launch(void* const* d_in, const int* in_sizes, int n_in,
                              void* d_out, int out_size) {
    const float* patches        = (const float*)d_in[0];
    const float* masked_token   = (const float*)d_in[3];
    const float* partial_params = (const float*)d_in[4];
    const float* emb_w          = (const float*)d_in[5];
    const float* emb_b          = (const float*)d_in[6];
    const float* ln1_g          = (const float*)d_in[7];
    const float* ln1_b          = (const float*)d_in[8];
    const float* in_proj_w      = (const float*)d_in[9];
    const float* in_proj_b      = (const float*)d_in[10];
    const float* out_proj_w     = (const float*)d_in[11];
    const float* out_proj_b     = (const float*)d_in[12];
    const float* rel_pos        = (const float*)d_in[13];
    const float* ln2_g          = (const float*)d_in[14];
    const float* ln2_b          = (const float*)d_in[15];
    const float* ffn_w1         = (const float*)d_in[16];
    const float* ffn_b1         = (const float*)d_in[17];
    const float* ffn_w2         = (const float*)d_in[18];
    const float* ffn_b2         = (const float*)d_in[19];
    const float* outp_w         = (const float*)d_in[20];
    const float* outp_b         = (const float*)d_in[21];
    float* out = (float*)d_out;

    float *x, *qkv;
    uint8_t *xn, *o, *h, *xf, *win, *wo, *w1, *w2, *wv;
    cudaGetSymbolAddress((void**)&x,   g_x);
    cudaGetSymbolAddress((void**)&qkv, g_qkv);
    cudaGetSymbolAddress((void**)&xn,  s_xn);
    cudaGetSymbolAddress((void**)&o,   s_o);
    cudaGetSymbolAddress((void**)&h,   s_h);
    cudaGetSymbolAddress((void**)&xf,  s_xf);
    cudaGetSymbolAddress((void**)&win, s_win);
    cudaGetSymbolAddress((void**)&wo,  s_wo);
    cudaGetSymbolAddress((void**)&w1,  s_w1);
    cudaGetSymbolAddress((void**)&w2,  s_w2);
    cudaGetSymbolAddress((void**)&wv,  s_wv);

    cudaFuncSetAttribute(attn_kernel, cudaFuncAttributeMaxDynamicSharedMemorySize, ATTN_SMEM);
    cudaFuncSetAttribute(gemm_split<64, 0>, cudaFuncAttributeMaxDynamicSharedMemorySize, 49152);
    cudaFuncSetAttribute(gemm_split<64, 1>, cudaFuncAttributeMaxDynamicSharedMemorySize, 49152);
    cudaFuncSetAttribute(gemm_split<128, 0>, cudaFuncAttributeMaxDynamicSharedMemorySize, 65536);
    cudaFuncSetAttribute(gemm_split<128, 2>, cudaFuncAttributeMaxDynamicSharedMemorySize, 65536);

    // ---- convert all weights to split tile format ----
    {
        int nc;
        nc = NL * 3 * ND * ND / 8;  convert_w<<<(nc + 255) / 256, 256>>>(in_proj_w,  win, ND, nc);
        nc = NL * ND * ND / 8;      convert_w<<<(nc + 255) / 256, 256>>>(out_proj_w, wo,  ND, nc);
        nc = NL * NF * ND / 8;      convert_w<<<(nc + 255) / 256, 256>>>(ffn_w1,     w1,  ND, nc);
        nc = NL * ND * NF / 8;      convert_w<<<(nc + 255) / 256, 256>>>(ffn_w2,     w2,  NF, nc);
        nc = (int)((size_t)NV * ND / 8);
        convert_w<<<(nc + 255) / 256, 256>>>(outp_w, wv, ND, nc);
    }

    tokenize_embed_kernel<<<NTOK, 128>>>(patches, masked_token, partial_params, emb_w, emb_b);

    for (int l = 0; l < NL; l++) {
        ln_kernel<<<NTOK, 256>>>(x, xn, ln1_g + l * ND, ln1_b + l * ND);

        gemm_split<64, 0><<<dim3(NTOK / 64, 3 * ND / 128), 256, 49152>>>(
            xn, win + (size_t)l * 3 * ND * ND * 4, in_proj_b + l * 3 * ND,
            nullptr, qkv, NTOK, 3 * ND, ND);

        attn_kernel<<<NB * NH * 2, 256, ATTN_SMEM>>>(rel_pos + (size_t)l * NS * NS);

        gemm_split<64, 1><<<dim3(NTOK / 64, ND / 128), 256, 49152>>>(
            o, wo + (size_t)l * ND * ND * 4, out_proj_b + l * ND,
            x, x, NTOK, ND, ND);

        ln_kernel<<<NTOK, 256>>>(x, xn, ln2_g + l * ND, ln2_b + l * ND);

        gemm_split<128, 2><<<dim3(NTOK / 128, NF / 128), 256, 65536>>>(
            xn, w1 + (size_t)l * NF * ND * 4, ffn_b1 + l * NF,
            nullptr, h, NTOK, NF, ND);

        gemm_split<64, 1><<<dim3(NTOK / 64, ND / 128), 256, 49152>>>(
            h, w2 + (size_t)l * ND * NF * 4, ffn_b2 + l * ND,
            x, x, NTOK, ND, NF);
    }

    convert_x_kernel<<<NTOK, 256>>>(x, xf);

    gemm_split<128, 0><<<dim3(NTOK / 128, NV / 128), 256, 65536>>>(
        xf, wv, outp_b, nullptr, out, NTOK, NV, ND);
}